// round 8
// baseline (speedup 1.0000x reference)
#include <cuda_runtime.h>
#include <cuda_bf16.h>
#include <cstdint>

// LearnedTaskSpecificLinear: out[n,o] = sum_i x[n,i] * W[task_ids[n], i, o]
// N_ROWS=2048, IN=OUT=512, NUM_TASKS=64.
//
// Block = (task, 128-col tile, m-slot), 128 threads. Deterministic row list
// (prefix scan). GEMM M=32 x N=128 x K=512, K_TILE=32.
// Per-thread tile 8 rows x 4 cols. W tiles cp.async double-buffered; x tiles
// register-prefetched + transposed scalar STS.
// xs rows padded to 36 floats (144B) so 16B vector reads stay aligned.

#define NUM_TASKS 64
#define N_ROWS    2048
#define IN_SIZE   512
#define OUT_SIZE  512

#define M_TILE 32
#define N_TILE 128
#define K_TILE 32
#define NTHREADS 128
#define N_KTILES (IN_SIZE / K_TILE)    // 16
#define M_SLOTS 2
#define PER_THREAD (N_ROWS / NTHREADS) // 16
#define XS_PAD 4                        // 36 floats/row = 144B, 16B-aligned

typedef unsigned long long ull;

__device__ __forceinline__ ull fma2(ull a, ull b, ull c) {
    ull d;
    asm("fma.rn.f32x2 %0, %1, %2, %3;" : "=l"(d) : "l"(a), "l"(b), "l"(c));
    return d;
}
__device__ __forceinline__ ull pack2(float lo, float hi) {
    ull d;
    asm("mov.b64 %0, {%1, %2};" : "=l"(d) : "f"(lo), "f"(hi));
    return d;
}
__device__ __forceinline__ void unpack2(ull v, float& lo, float& hi) {
    asm("mov.b64 {%0, %1}, %2;" : "=f"(lo), "=f"(hi) : "l"(v));
}
__device__ __forceinline__ void cp16(uint32_t dst_smem, const void* src) {
    asm volatile("cp.async.cg.shared.global [%0], [%1], 16;\n"
                 :: "r"(dst_smem), "l"(src));
}
__device__ __forceinline__ void cp_commit() {
    asm volatile("cp.async.commit_group;\n");
}
__device__ __forceinline__ void cp_wait1() {
    asm volatile("cp.async.wait_group 1;\n");
}

__global__ __launch_bounds__(NTHREADS, 4)
void task_linear_kernel(const float* __restrict__ x,
                        const int* __restrict__ tid32,
                        const float* __restrict__ W,
                        float* __restrict__ out) {
    const int t    = blockIdx.x;
    const int ct   = blockIdx.y;
    const int slot = blockIdx.z;
    const int tid  = threadIdx.x;
    const int lane = tid & 31;   // col-group: 4 cols at lane*4
    const int w    = tid >> 5;   // row-group: 8 rows at w*8

    __shared__ unsigned short rows[N_ROWS];
    __shared__ int s_is64;
    __shared__ int warp_sums[NTHREADS / 32];
    __shared__ int s_n;
    // xs[buf][kk][r]: transposed; 36-float rows keep every 16B read aligned.
    __shared__ __align__(16) float xs[2][K_TILE][M_TILE + XS_PAD];
    __shared__ __align__(16) float ws[2][K_TILE][N_TILE];

    if (tid == 0) s_is64 = 0;
    __syncthreads();

    // dtype detect (int32 vs int64): odd-index words of int64 data are zero.
    {
        int v = 0;
        for (int i = tid; i < 256; i += NTHREADS) v |= tid32[2 * i + 1];
        #pragma unroll
        for (int o = 16; o > 0; o >>= 1) v |= __shfl_xor_sync(0xffffffffu, v, o);
        if (lane == 0 && v == 0) s_is64 = 1;
    }
    __syncthreads();
    const int stride = s_is64 ? 2 : 1;

    // Deterministic row list (index order) via prefix scan.
    {
        const int base = tid * PER_THREAD;
        int match = 0;
        #pragma unroll
        for (int j = 0; j < PER_THREAD; j++)
            if (tid32[(base + j) * stride] == t) match |= (1 << j);
        int c = __popc(match);
        int incl = c;
        #pragma unroll
        for (int o = 1; o < 32; o <<= 1) {
            int v = __shfl_up_sync(0xffffffffu, incl, o);
            if (lane >= o) incl += v;
        }
        if (lane == 31) warp_sums[w] = incl;
        __syncthreads();
        int warp_off = 0;
        #pragma unroll
        for (int q = 0; q < NTHREADS / 32; q++)
            if (q < w) warp_off += warp_sums[q];
        int pos = warp_off + incl - c;
        #pragma unroll
        for (int j = 0; j < PER_THREAD; j++)
            if (match & (1 << j)) rows[pos++] = (unsigned short)(base + j);
        if (tid == NTHREADS - 1) s_n = pos;
    }
    __syncthreads();
    const int n = s_n;

    const float* Wbase = W + ((size_t)t * IN_SIZE) * OUT_SIZE + (size_t)ct * N_TILE;

    uint32_t ws_base = (uint32_t)__cvta_generic_to_shared(&ws[0][0][0]);
    const uint32_t WS_BUF = K_TILE * N_TILE * 4;

    for (int m0 = slot * M_TILE; m0 < n; m0 += M_SLOTS * M_TILE) {
        ull acc[4][4];
        #pragma unroll
        for (int rp = 0; rp < 4; rp++)
            #pragma unroll
            for (int c = 0; c < 4; c++) acc[rp][c] = 0ULL;

        int   xr[2]; int xc4[2]; bool xp[2]; const float* xptr[2];
        #pragma unroll
        for (int q = 0; q < 2; q++) {
            int chunk = tid + q * NTHREADS;     // 0..255
            xr[q]  = chunk >> 3;                // 0..31
            xc4[q] = chunk & 7;                 // 0..7
            xp[q]  = (m0 + xr[q]) < n;
            xptr[q] = x + (size_t)(xp[q] ? rows[m0 + xr[q]] : 0) * IN_SIZE + xc4[q] * 4;
        }

        float4 xreg[2];

        auto ldg_x = [&](int kt) {
            #pragma unroll
            for (int q = 0; q < 2; q++)
                xreg[q] = xp[q] ? *(const float4*)(xptr[q] + kt * K_TILE)
                                : make_float4(0.f, 0.f, 0.f, 0.f);
        };
        auto sts_x = [&](int buf) {
            #pragma unroll
            for (int q = 0; q < 2; q++) {
                xs[buf][xc4[q] * 4 + 0][xr[q]] = xreg[q].x;
                xs[buf][xc4[q] * 4 + 1][xr[q]] = xreg[q].y;
                xs[buf][xc4[q] * 4 + 2][xr[q]] = xreg[q].z;
                xs[buf][xc4[q] * 4 + 3][xr[q]] = xreg[q].w;
            }
        };
        auto cp_w = [&](int kt, int buf) {
            const int k0 = kt * K_TILE;
            #pragma unroll
            for (int q = 0; q < 8; q++) {
                int j  = tid + q * NTHREADS;   // 0..1023
                int kk = j >> 5;
                int c4 = j & 31;
                cp16(ws_base + buf * WS_BUF + (uint32_t)(kk * N_TILE + c4 * 4) * 4,
                     Wbase + (size_t)(k0 + kk) * OUT_SIZE + c4 * 4);
            }
        };

        // prologue: x0 staged directly; ws0, ws1 in flight
        ldg_x(0);
        sts_x(0);
        cp_w(0, 0); cp_commit();
        ldg_x(1);
        cp_w(1, 1); cp_commit();

        for (int kt = 0; kt < N_KTILES; kt++) {
            const int buf = kt & 1;
            cp_wait1();          // ws tile kt complete (this thread's groups)
            __syncthreads();     // ... and everyone's; x STS of kt visible

            if (kt + 1 < N_KTILES) sts_x(buf ^ 1);   // stage x(kt+1) (in regs)
            if (kt + 2 < N_KTILES) ldg_x(kt + 2);    // fetch x(kt+2) over compute

            #pragma unroll 8
            for (int kk = 0; kk < K_TILE; kk++) {
                ulonglong2 A0 = *(const ulonglong2*)&xs[buf][kk][w * 8];     // rows 0-3
                ulonglong2 A1 = *(const ulonglong2*)&xs[buf][kk][w * 8 + 4]; // rows 4-7
                float4 b4 = *(const float4*)&ws[buf][kk][lane * 4];
                ull b0 = pack2(b4.x, b4.x);
                ull b1 = pack2(b4.y, b4.y);
                ull b2 = pack2(b4.z, b4.z);
                ull b3 = pack2(b4.w, b4.w);
                acc[0][0] = fma2(A0.x, b0, acc[0][0]);
                acc[0][1] = fma2(A0.x, b1, acc[0][1]);
                acc[0][2] = fma2(A0.x, b2, acc[0][2]);
                acc[0][3] = fma2(A0.x, b3, acc[0][3]);
                acc[1][0] = fma2(A0.y, b0, acc[1][0]);
                acc[1][1] = fma2(A0.y, b1, acc[1][1]);
                acc[1][2] = fma2(A0.y, b2, acc[1][2]);
                acc[1][3] = fma2(A0.y, b3, acc[1][3]);
                acc[2][0] = fma2(A1.x, b0, acc[2][0]);
                acc[2][1] = fma2(A1.x, b1, acc[2][1]);
                acc[2][2] = fma2(A1.x, b2, acc[2][2]);
                acc[2][3] = fma2(A1.x, b3, acc[2][3]);
                acc[3][0] = fma2(A1.y, b0, acc[3][0]);
                acc[3][1] = fma2(A1.y, b1, acc[3][1]);
                acc[3][2] = fma2(A1.y, b2, acc[3][2]);
                acc[3][3] = fma2(A1.y, b3, acc[3][3]);
            }
            __syncthreads();     // all reads of buf done before refill

            if (kt + 2 < N_KTILES) cp_w(kt + 2, buf);
            cp_commit();         // empty commits keep group accounting uniform
        }

        // epilogue: 8 rows x 4 cols per thread
        #pragma unroll
        for (int rp = 0; rp < 4; rp++) {
            float lo0, hi0, lo1, hi1, lo2, hi2, lo3, hi3;
            unpack2(acc[rp][0], lo0, hi0);
            unpack2(acc[rp][1], lo1, hi1);
            unpack2(acc[rp][2], lo2, hi2);
            unpack2(acc[rp][3], lo3, hi3);
            int r0 = m0 + w * 8 + rp * 2;
            if (r0 < n) {
                float4 v = make_float4(lo0, lo1, lo2, lo3);
                *(float4*)&out[(size_t)rows[r0] * OUT_SIZE + ct * N_TILE + lane * 4] = v;
            }
            int r1 = r0 + 1;
            if (r1 < n) {
                float4 v = make_float4(hi0, hi1, hi2, hi3);
                *(float4*)&out[(size_t)rows[r1] * OUT_SIZE + ct * N_TILE + lane * 4] = v;
            }
        }
    }
}

extern "C" void kernel_launch(void* const* d_in, const int* in_sizes, int n_in,
                              void* d_out, int out_size) {
    const float* x = nullptr;
    const int*   tids = nullptr;
    const float* W = nullptr;
    for (int i = 0; i < n_in; i++) {
        if (in_sizes[i] == N_ROWS * IN_SIZE)                    x = (const float*)d_in[i];
        else if (in_sizes[i] == N_ROWS)                         tids = (const int*)d_in[i];
        else if (in_sizes[i] == NUM_TASKS * IN_SIZE * OUT_SIZE) W = (const float*)d_in[i];
    }
    float* out = (float*)d_out;

    dim3 grid(NUM_TASKS, OUT_SIZE / N_TILE, M_SLOTS);  // 64 x 4 x 2 = 512 blocks
    task_linear_kernel<<<grid, NTHREADS>>>(x, tids, W, out);
}

// round 12
// speedup vs baseline: 1.5376x; 1.5376x over previous
#include <cuda_runtime.h>
#include <cuda_bf16.h>
#include <cstdint>

// LearnedTaskSpecificLinear via mma.sync (HMMA) bf16 split precision.
// out[n,o] = sum_i x[n,i] * W[task_ids[n], i, o],  N=2048, I=O=512, T=64.
// (tcgen05 is sm_103a-only; harness targets sm_103 -> use baseline mma.sync.)
//
// Block = (task, 128-col tile), 256 threads (8 warps = 2m x 4n).
// M_TILE=64 (rows zero-padded), N_TILE=128, K staged 64 at a time.
// Split: v = hi(bf16) + lo(bf16 residual); acc += Ah*Bh + Ah*Bl + Al*Bh (fp32).
// A smem [m][k], B smem [n][k] (transposed during conversion), SW128 swizzle,
// fragments via ldmatrix.x4. W read from HBM exactly once per block.

#define NUM_TASKS 64
#define N_ROWS    2048
#define IN_SIZE   512
#define OUT_SIZE  512

#define NT        256
#define PER_THREAD (N_ROWS / NT)     // 8
#define M_TILE    64
#define N_TILE    128
#define K_TILE    64
#define N_STAGES  (IN_SIZE / K_TILE) // 8

// dynamic smem layout (all tiles have 128-byte rows: 64 bf16)
#define OFF_A_HI  0
#define OFF_A_LO  (OFF_A_HI + M_TILE * 128)     //  8192
#define OFF_B_HI  (OFF_A_LO + M_TILE * 128)     // 16384
#define OFF_B_LO  (OFF_B_HI + N_TILE * 128)     // 32768
#define DYN_SMEM  (OFF_B_LO + N_TILE * 128)     // 49152

typedef unsigned long long ull;

static __device__ __forceinline__ uint32_t swz(uint32_t o) {
    return o ^ ((o >> 3) & 0x70);
}
static __device__ __forceinline__ uint32_t smem_u32(const void* p) {
    uint32_t a;
    asm("{ .reg .u64 t; cvta.to.shared.u64 t, %1; cvt.u32.u64 %0, t; }"
        : "=r"(a) : "l"(p));
    return a;
}
// pack: e0 -> low half, e1 -> high half
static __device__ __forceinline__ uint32_t bfhi(float e0, float e1) {
    uint32_t r;
    asm("cvt.rn.bf16x2.f32 %0, %1, %2;" : "=r"(r) : "f"(e1), "f"(e0));
    return r;
}
static __device__ __forceinline__ uint32_t bflo(float e0, float e1, uint32_t h) {
    float h0 = __uint_as_float(h << 16);
    float h1 = __uint_as_float(h & 0xffff0000u);
    return bfhi(e0 - h0, e1 - h1);
}
static __device__ __forceinline__ void ldsm_x4(uint32_t& r0, uint32_t& r1,
                                               uint32_t& r2, uint32_t& r3,
                                               uint32_t addr) {
    asm volatile("ldmatrix.sync.aligned.m8n8.x4.shared.b16 {%0,%1,%2,%3}, [%4];"
                 : "=r"(r0), "=r"(r1), "=r"(r2), "=r"(r3) : "r"(addr));
}
static __device__ __forceinline__ void mma_bf16(float* d, const uint32_t* a,
                                                uint32_t b0, uint32_t b1) {
    asm volatile(
        "mma.sync.aligned.m16n8k16.row.col.f32.bf16.bf16.f32 "
        "{%0,%1,%2,%3}, {%4,%5,%6,%7}, {%8,%9}, {%0,%1,%2,%3};"
        : "+f"(d[0]), "+f"(d[1]), "+f"(d[2]), "+f"(d[3])
        : "r"(a[0]), "r"(a[1]), "r"(a[2]), "r"(a[3]), "r"(b0), "r"(b1));
}

__global__ __launch_bounds__(NT)
void task_linear_mma_kernel(const float* __restrict__ x,
                            const int* __restrict__ tid32,
                            const float* __restrict__ W,
                            float* __restrict__ out) {
    extern __shared__ __align__(128) char dsm[];
    const int t    = blockIdx.x;
    const int ct   = blockIdx.y;
    const int tid  = threadIdx.x;
    const int lane = tid & 31;
    const int wid  = tid >> 5;
    const int mw   = wid >> 2;     // warp m-half (0/1): rows mw*32..+32
    const int nw   = wid & 3;      // warp n-quarter: cols nw*32..+32

    __shared__ unsigned short rows[N_ROWS];
    __shared__ int warp_sums[NT / 32];
    __shared__ int s_n, s_is64;

    const uint32_t sb = smem_u32(dsm);

    if (tid == 0) s_is64 = 0;
    __syncthreads();

    // dtype detect (int32 vs int64): odd-index words of int64 data are zero.
    {
        int v = 0;
        for (int i = tid; i < 256; i += NT) v |= tid32[2 * i + 1];
        #pragma unroll
        for (int o = 16; o > 0; o >>= 1) v |= __shfl_xor_sync(0xffffffffu, v, o);
        if (lane == 0 && v == 0) s_is64 = 1;
    }
    __syncthreads();
    const int stride = s_is64 ? 2 : 1;

    // Deterministic row list (index order) via prefix scan.
    {
        const int base = tid * PER_THREAD;
        int match = 0;
        #pragma unroll
        for (int j = 0; j < PER_THREAD; j++)
            if (tid32[(base + j) * stride] == t) match |= (1 << j);
        int c = __popc(match);
        int incl = c;
        #pragma unroll
        for (int o = 1; o < 32; o <<= 1) {
            int v = __shfl_up_sync(0xffffffffu, incl, o);
            if (lane >= o) incl += v;
        }
        if (lane == 31) warp_sums[wid] = incl;
        __syncthreads();
        int woff = 0;
        #pragma unroll
        for (int q = 0; q < NT / 32; q++)
            if (q < wid) woff += warp_sums[q];
        int pos = woff + incl - c;
        #pragma unroll
        for (int j = 0; j < PER_THREAD; j++)
            if (match & (1 << j)) rows[pos++] = (unsigned short)(base + j);
        if (tid == NT - 1) s_n = pos;
    }
    __syncthreads();
    const int n = s_n;

    // Conversion thread mappings (constant):
    //   A: row ar = tid&63, k-quarter aq = tid>>6 (16 floats each)
    //   B: col bn = tid&127, k-half bq = tid>>7 (32 k each)
    const int ar = tid & 63;
    const int aq = tid >> 6;
    const int bn = tid & 127;
    const int bq = tid >> 7;

    for (int m0 = 0; m0 < n; m0 += M_TILE) {
        float acc[2][4][4];
        #pragma unroll
        for (int tm = 0; tm < 2; tm++)
            #pragma unroll
            for (int tn = 0; tn < 4; tn++)
                #pragma unroll
                for (int c = 0; c < 4; c++) acc[tm][tn][c] = 0.f;

        const bool avalid = (m0 + ar) < n;
        const float* xrow = x + (size_t)(avalid ? rows[m0 + ar] : 0) * IN_SIZE;

        for (int st = 0; st < N_STAGES; st++) {
            const int kbase = st * K_TILE;

            // ---- convert A: x[m0..][kbase + aq*16 .. +16] -> bf16 hi/lo ----
            {
                const float* xp = xrow + kbase + aq * 16;
                #pragma unroll
                for (int j = 0; j < 4; j++) {
                    float4 v = avalid ? *(const float4*)(xp + j * 4)
                                      : make_float4(0.f, 0.f, 0.f, 0.f);
                    uint32_t h0 = bfhi(v.x, v.y), h1 = bfhi(v.z, v.w);
                    uint32_t l0 = bflo(v.x, v.y, h0), l1 = bflo(v.z, v.w, h1);
                    uint32_t off = swz((uint32_t)(ar * 128 + (aq * 16 + j * 4) * 2));
                    *(ull*)(dsm + OFF_A_HI + off) = ((ull)h1 << 32) | h0;
                    *(ull*)(dsm + OFF_A_LO + off) = ((ull)l1 << 32) | l0;
                }
            }
            // ---- convert B: W[k][n] -> smem [n][k] bf16 hi/lo (transpose) ----
            {
                const float* wcol = W + ((size_t)t * IN_SIZE + kbase + bq * 32) * OUT_SIZE
                                      + (size_t)ct * N_TILE + bn;
                #pragma unroll
                for (int p = 0; p < 16; p++) {
                    float e0 = wcol[(size_t)(2 * p) * OUT_SIZE];
                    float e1 = wcol[(size_t)(2 * p + 1) * OUT_SIZE];
                    uint32_t h = bfhi(e0, e1);
                    uint32_t l = bflo(e0, e1, h);
                    uint32_t off = swz((uint32_t)(bn * 128 + (bq * 32 + 2 * p) * 2));
                    *(uint32_t*)(dsm + OFF_B_HI + off) = h;
                    *(uint32_t*)(dsm + OFF_B_LO + off) = l;
                }
            }
            __syncthreads();

            // ---- 4 k16 steps of HMMA ----
            #pragma unroll
            for (int ks = 0; ks < 4; ks++) {
                const int k0 = ks * 16;
                const uint32_t kcol = (uint32_t)((k0 + ((lane >> 4) & 1) * 8) * 2);

                uint32_t ah[2][4], al[2][4], bh[2][4], bl[2][4];
                #pragma unroll
                for (int tm = 0; tm < 2; tm++) {
                    uint32_t off = swz((uint32_t)((mw * 32 + tm * 16 + (lane & 15)) * 128) + kcol);
                    ldsm_x4(ah[tm][0], ah[tm][1], ah[tm][2], ah[tm][3],
                            sb + OFF_A_HI + off);
                    ldsm_x4(al[tm][0], al[tm][1], al[tm][2], al[tm][3],
                            sb + OFF_A_LO + off);
                }
                #pragma unroll
                for (int tp = 0; tp < 2; tp++) {
                    uint32_t off = swz((uint32_t)((nw * 32 + tp * 16 + (lane & 15)) * 128) + kcol);
                    ldsm_x4(bh[tp][0], bh[tp][1], bh[tp][2], bh[tp][3],
                            sb + OFF_B_HI + off);
                    ldsm_x4(bl[tp][0], bl[tp][1], bl[tp][2], bl[tp][3],
                            sb + OFF_B_LO + off);
                }
                #pragma unroll
                for (int tm = 0; tm < 2; tm++) {
                    #pragma unroll
                    for (int tn = 0; tn < 4; tn++) {
                        const int tp = tn >> 1, sl = tn & 1;
                        mma_bf16(acc[tm][tn], ah[tm], bh[tp][sl], bh[tp][2 + sl]);
                        mma_bf16(acc[tm][tn], ah[tm], bl[tp][sl], bl[tp][2 + sl]);
                        mma_bf16(acc[tm][tn], al[tm], bh[tp][sl], bh[tp][2 + sl]);
                    }
                }
            }
            __syncthreads();   // tiles consumed before next stage overwrites
        }

        // ---- epilogue: D fragments -> out ----
        // d0,d1: row lane/4,   cols (lane&3)*2 + {0,1}
        // d2,d3: row lane/4+8, same cols
        #pragma unroll
        for (int tm = 0; tm < 2; tm++) {
            #pragma unroll
            for (int tn = 0; tn < 4; tn++) {
                const int col = ct * N_TILE + nw * 32 + tn * 8 + (lane & 3) * 2;
                int m_lo = m0 + mw * 32 + tm * 16 + (lane >> 2);
                if (m_lo < n) {
                    float* o = out + (size_t)rows[m_lo] * OUT_SIZE + col;
                    o[0] = acc[tm][tn][0];
                    o[1] = acc[tm][tn][1];
                }
                int m_hi = m_lo + 8;
                if (m_hi < n) {
                    float* o = out + (size_t)rows[m_hi] * OUT_SIZE + col;
                    o[0] = acc[tm][tn][2];
                    o[1] = acc[tm][tn][3];
                }
            }
        }
        __syncthreads();   // smem reuse safety across m-tiles
    }
}

extern "C" void kernel_launch(void* const* d_in, const int* in_sizes, int n_in,
                              void* d_out, int out_size) {
    const float* x = nullptr;
    const int*   tids = nullptr;
    const float* W = nullptr;
    for (int i = 0; i < n_in; i++) {
        if (in_sizes[i] == N_ROWS * IN_SIZE)                    x = (const float*)d_in[i];
        else if (in_sizes[i] == N_ROWS)                         tids = (const int*)d_in[i];
        else if (in_sizes[i] == NUM_TASKS * IN_SIZE * OUT_SIZE) W = (const float*)d_in[i];
    }
    float* out = (float*)d_out;

    cudaFuncSetAttribute(task_linear_mma_kernel,
                         cudaFuncAttributeMaxDynamicSharedMemorySize, DYN_SMEM);
    dim3 grid(NUM_TASKS, OUT_SIZE / N_TILE);   // 64 x 4 = 256 blocks
    task_linear_mma_kernel<<<grid, NT, DYN_SMEM>>>(x, tids, W, out);
}